// round 2
// baseline (speedup 1.0000x reference)
#include <cuda_runtime.h>
#include <cstdint>

#define T_STEPS 512

__device__ uint2    g_keys[T_STEPS];
__device__ unsigned g_spk[T_STEPS * 1024];   // [t][b*32 + word]

// ---------------- threefry2x32 (JAX), 20 rounds ----------------
__device__ __forceinline__ void threefry(unsigned k0, unsigned k1,
                                         unsigned x0, unsigned x1,
                                         unsigned &o0, unsigned &o1)
{
    unsigned k2 = k0 ^ k1 ^ 0x1BD11BDAu;
    x0 += k0; x1 += k1;
#define TF_R(r) { x0 += x1; x1 = __funnelshift_l(x1, x1, (r)); x1 ^= x0; }
    TF_R(13) TF_R(15) TF_R(26) TF_R(6)
    x0 += k1; x1 += k2 + 1u;
    TF_R(17) TF_R(29) TF_R(16) TF_R(24)
    x0 += k2; x1 += k0 + 2u;
    TF_R(13) TF_R(15) TF_R(26) TF_R(6)
    x0 += k0; x1 += k1 + 3u;
    TF_R(17) TF_R(29) TF_R(16) TF_R(24)
    x0 += k1; x1 += k2 + 4u;
    TF_R(13) TF_R(15) TF_R(26) TF_R(6)
    x0 += k2; x1 += k0 + 5u;
#undef TF_R
    o0 = x0; o1 = x1;
}

__global__ void keys_kernel()
{
    int t = threadIdx.x;
    if (t < T_STEPS) {
        unsigned a, b;
        threefry(0u, 1u, 0u, (unsigned)t, a, b);   // split(key(1), 512), partitionable
        g_keys[t] = make_uint2(a, b);
    }
}

__global__ void __launch_bounds__(256) spikes_kernel(const float* __restrict__ image)
{
    unsigned gid = blockIdx.x * 256u + threadIdx.x;   // 512 * 32768
    unsigned t = gid >> 15;
    unsigned i = gid & 32767u;
    uint2 k = g_keys[t];
    unsigned o0, o1;
    threefry(k.x, k.y, 0u, i, o0, o1);
    unsigned bits = o0 ^ o1;                          // partitionable random_bits(32)
    float u = __uint_as_float(0x3f800000u | (bits >> 9)) - 1.0f;
    float r = __ldg(image + i) * 0.1953125f;          // == (image*200)*2^-10 bit-exact
    unsigned word = __ballot_sync(0xffffffffu, r > u);
    if ((threadIdx.x & 31u) == 0u)
        g_spk[t * 1024u + (i >> 5)] = word;
}

// ---------------- persistent sim: 1 CTA / batch ----------------
#define SM_XF    0
#define SM_M1A   1024
#define SM_M2A   5728
#define SM_SKA   10432
#define SM_M1B   15136
#define SM_M2B   16312
#define SM_SKB   17488
#define SM_M1C   18664
#define SM_M2C   20264
#define SM_SKC   21864
#define SM_M1D   23464
#define SM_M2D   23864
#define SM_SKD   24264
#define SM_M1E   24664
#define SM_M2E   24784
#define SM_SKE   24904
#define SM_M1F   25024
#define SM_M2F   25108
#define SM_SKF   25192
#define SM_M1G   25276
#define SM_M2G   25286
#define SM_SKG   25296
#define SM_ACC   25306
#define SM_ZEND  25316
#define SM_W1    25316
#define SM_W2    25466
#define SM_FW1   27866
#define SM_FW2   37946
#define SM_PART  38786
#define SM_TOTAL 48386
#define SMEM_BYTES (SM_TOTAL * 4)

__device__ __forceinline__ void lif(float* m1, float* m2, float* s, float drive)
{
    float oms = 1.0f - *s;
    float nm1 = (*m1) * 0.25f * oms + drive;
    float nm2 = (*m2) * 0.25f * oms + 0.5f * nm1;
    *m1 = nm1;
    *m2 = nm2;
    *s  = (nm2 > 0.3f) ? 1.0f : 0.0f;
}

__global__ void __launch_bounds__(1024, 1)
sim_kernel(const float* __restrict__ w1, const float* __restrict__ w2,
           const float* __restrict__ w3, const float* __restrict__ fw1,
           const float* __restrict__ fw2, float* __restrict__ out)
{
    extern __shared__ float sm[];
    const int tid = threadIdx.x;
    const int b   = blockIdx.x;

    for (int i = tid; i < 150;   i += 1024) sm[SM_W1  + i] = w1[i];
    for (int i = tid; i < 2400;  i += 1024) sm[SM_W2  + i] = w2[i];
    for (int i = tid; i < 10080; i += 1024) sm[SM_FW1 + i] = fw1[i];
    for (int i = tid; i < 840;   i += 1024) sm[SM_FW2 + i] = fw2[i];
    for (int i = tid; i < (SM_ZEND - SM_M1A); i += 1024) sm[SM_M1A + i] = 0.0f;
    __syncthreads();

    // static mappings
    const int c1_c  = tid / 112;              // conv1: tid<672
    const int c1_r  = tid % 112;
    const int c1_oy = c1_r >> 2;
    const int c1_x0 = (c1_r & 3) * 7;
    const int c2_o  = tid / 60;               // conv2 partials: tid<960
    const int c2_rr = tid % 60;
    const int c2_c  = c2_rr / 10;
    const int c2_oy = c2_rr % 10;
    const int g8    = tid >> 3;               // 8-lane groups
    const int j8    = tid & 7;
    const int wrp   = tid >> 5;
    const int lane  = tid & 31;

    const unsigned* spk_base = g_spk + b * 32;

#pragma unroll 1
    for (int t = 0; t < T_STEPS; t++) {
        // P0: expand input spikes
        {
            unsigned w = __ldg(spk_base + (unsigned)t * 1024u + (tid >> 5));
            sm[SM_XF + tid] = (float)((w >> (tid & 31)) & 1u);
        }
        __syncthreads();

        // P1: conv1 (1->6, 28x28) + LIF1
        if (tid < 672) {
            const float* wr = sm + SM_W1 + c1_c * 25;
            float acc[7];
#pragma unroll
            for (int o = 0; o < 7; o++) acc[o] = 0.0f;
#pragma unroll
            for (int ky = 0; ky < 5; ky++) {
                const float* row = sm + SM_XF + (c1_oy + ky) * 32 + c1_x0;
                float in[11];
#pragma unroll
                for (int q = 0; q < 11; q++) in[q] = row[q];
#pragma unroll
                for (int kx = 0; kx < 5; kx++) {
                    float wv = wr[ky * 5 + kx];
#pragma unroll
                    for (int o = 0; o < 7; o++) acc[o] = fmaf(wv, in[kx + o], acc[o]);
                }
            }
            int base = c1_c * 784 + c1_oy * 28 + c1_x0;
#pragma unroll
            for (int o = 0; o < 7; o++)
                lif(sm + SM_M1A + base + o, sm + SM_M2A + base + o, sm + SM_SKA + base + o, acc[o]);
        }
        __syncthreads();

        // P2: avgpool 28->14 + LIF2
        if (tid < 1176) {
            int c = tid / 196, r = tid % 196, py = r / 14, px = r % 14;
            const float* s1 = sm + SM_SKA + c * 784 + 2 * py * 28 + 2 * px;
            float d = 0.25f * (s1[0] + s1[1] + s1[28] + s1[29]);
            lif(sm + SM_M1B + tid, sm + SM_M2B + tid, sm + SM_SKB + tid, d);
        }
        __syncthreads();

        // P3: conv2 per-ic partials (16 oc x 6 ic x 10 oy, 10 outputs each)
        if (tid < 960) {
            const float* wr = sm + SM_W2 + c2_o * 150 + c2_c * 25;
            const float* ib = sm + SM_SKB + c2_c * 196;
            float acc[10];
#pragma unroll
            for (int o = 0; o < 10; o++) acc[o] = 0.0f;
#pragma unroll
            for (int ky = 0; ky < 5; ky++) {
                const float* row = ib + (c2_oy + ky) * 14;
                float in[14];
#pragma unroll
                for (int q = 0; q < 14; q++) in[q] = row[q];
#pragma unroll
                for (int kx = 0; kx < 5; kx++) {
                    float wv = wr[ky * 5 + kx];
#pragma unroll
                    for (int o = 0; o < 10; o++) acc[o] = fmaf(wv, in[kx + o], acc[o]);
                }
            }
            float* pp = sm + SM_PART + c2_c * 1600 + c2_o * 100 + c2_oy * 10;
#pragma unroll
            for (int o = 0; o < 10; o++) pp[o] = acc[o];
        }
        __syncthreads();

        // P4: reduce partials over ic + LIF3 (1600 outputs)
        for (int i = tid; i < 1600; i += 1024) {
            float d = 0.0f;
#pragma unroll
            for (int ic = 0; ic < 6; ic++) d += sm[SM_PART + ic * 1600 + i];
            lif(sm + SM_M1C + i, sm + SM_M2C + i, sm + SM_SKC + i, d);
        }
        __syncthreads();

        // P5: avgpool 10->5 + LIF4
        if (tid < 400) {
            int c = tid / 25, r = tid % 25, py = r / 5, px = r % 5;
            const float* s3 = sm + SM_SKC + c * 100 + 2 * py * 10 + 2 * px;
            float d = 0.25f * (s3[0] + s3[1] + s3[10] + s3[11]);
            lif(sm + SM_M1D + tid, sm + SM_M2D + tid, sm + SM_SKD + tid, d);
        }
        __syncthreads();

        // P6: conv3 == dense 120x400 (w3 from global/L2) + LIF5
        if (tid < 960) {
            const float* wp = w3 + g8 * 400;
            float s = 0.0f;
#pragma unroll
            for (int k = j8; k < 400; k += 8) s = fmaf(__ldg(wp + k), sm[SM_SKD + k], s);
            s += __shfl_xor_sync(0xffffffffu, s, 4);
            s += __shfl_xor_sync(0xffffffffu, s, 2);
            s += __shfl_xor_sync(0xffffffffu, s, 1);
            if (j8 == 0)
                lif(sm + SM_M1E + g8, sm + SM_M2E + g8, sm + SM_SKE + g8, s);
        }
        __syncthreads();

        // P7: fc1 84x120 + LIF6
        if (tid < 672) {
            const float* wp = sm + SM_FW1 + g8 * 120;
            float s = 0.0f;
#pragma unroll
            for (int k = j8; k < 120; k += 8) s = fmaf(wp[k], sm[SM_SKE + k], s);
            s += __shfl_xor_sync(0xffffffffu, s, 4);
            s += __shfl_xor_sync(0xffffffffu, s, 2);
            s += __shfl_xor_sync(0xffffffffu, s, 1);
            if (j8 == 0)
                lif(sm + SM_M1F + g8, sm + SM_M2F + g8, sm + SM_SKF + g8, s);
        }
        __syncthreads();

        // P8: fc2 10x84 + LIF7 + acc (warps 0..9)
        if (wrp < 10) {
            const float* wp = sm + SM_FW2 + wrp * 84;
            float s = 0.0f;
            for (int k = lane; k < 84; k += 32) s = fmaf(wp[k], sm[SM_SKF + k], s);
#pragma unroll
            for (int d = 16; d > 0; d >>= 1) s += __shfl_xor_sync(0xffffffffu, s, d);
            if (lane == 0) {
                lif(sm + SM_M1G + wrp, sm + SM_M2G + wrp, sm + SM_SKG + wrp, s);
                sm[SM_ACC + wrp] += sm[SM_SKG + wrp];
            }
        }
        __syncthreads();
    }

    if (tid < 10)
        out[b * 10 + tid] = sm[SM_ACC + tid] * (1.0f / 512.0f);
}

extern "C" void kernel_launch(void* const* d_in, const int* in_sizes, int n_in,
                              void* d_out, int out_size)
{
    const float* image = (const float*)d_in[0];
    const float* w1    = (const float*)d_in[1];
    const float* w2    = (const float*)d_in[2];
    const float* w3    = (const float*)d_in[3];
    const float* fw1   = (const float*)d_in[4];
    const float* fw2   = (const float*)d_in[5];
    float* out = (float*)d_out;

    keys_kernel<<<1, 512>>>();
    spikes_kernel<<<(T_STEPS * 32768) / 256, 256>>>(image);
    cudaFuncSetAttribute(sim_kernel, cudaFuncAttributeMaxDynamicSharedMemorySize, SMEM_BYTES);
    sim_kernel<<<32, 1024, SMEM_BYTES>>>(w1, w2, w3, fw1, fw2, out);
}

// round 3
// speedup vs baseline: 1.4849x; 1.4849x over previous
#include <cuda_runtime.h>
#include <cstdint>

#define T_STEPS 512

__device__ uint2    g_keys[T_STEPS];
__device__ unsigned g_spk[T_STEPS * 1024];     // [t][b*32 + word]
__device__ float    g_w3t[400 * 120];          // transposed conv3 weights [k][o]

// ---------------- threefry2x32 (JAX), 20 rounds ----------------
__device__ __forceinline__ void threefry(unsigned k0, unsigned k1,
                                         unsigned x0, unsigned x1,
                                         unsigned &o0, unsigned &o1)
{
    unsigned k2 = k0 ^ k1 ^ 0x1BD11BDAu;
    x0 += k0; x1 += k1;
#define TF_R(r) { x0 += x1; x1 = __funnelshift_l(x1, x1, (r)); x1 ^= x0; }
    TF_R(13) TF_R(15) TF_R(26) TF_R(6)
    x0 += k1; x1 += k2 + 1u;
    TF_R(17) TF_R(29) TF_R(16) TF_R(24)
    x0 += k2; x1 += k0 + 2u;
    TF_R(13) TF_R(15) TF_R(26) TF_R(6)
    x0 += k0; x1 += k1 + 3u;
    TF_R(17) TF_R(29) TF_R(16) TF_R(24)
    x0 += k1; x1 += k2 + 4u;
    TF_R(13) TF_R(15) TF_R(26) TF_R(6)
    x0 += k2; x1 += k0 + 5u;
#undef TF_R
    o0 = x0; o1 = x1;
}

__global__ void keys_kernel()
{
    int t = threadIdx.x;
    if (t < T_STEPS) {
        unsigned a, b;
        threefry(0u, 1u, 0u, (unsigned)t, a, b);
        g_keys[t] = make_uint2(a, b);
    }
}

__global__ void __launch_bounds__(256) spikes_kernel(const float* __restrict__ image)
{
    unsigned gid = blockIdx.x * 256u + threadIdx.x;
    unsigned t = gid >> 15;
    unsigned i = gid & 32767u;
    uint2 k = g_keys[t];
    unsigned o0, o1;
    threefry(k.x, k.y, 0u, i, o0, o1);
    unsigned bits = o0 ^ o1;
    float u = __uint_as_float(0x3f800000u | (bits >> 9)) - 1.0f;
    float r = __ldg(image + i) * 0.1953125f;
    unsigned word = __ballot_sync(0xffffffffu, r > u);
    if ((threadIdx.x & 31u) == 0u)
        g_spk[t * 1024u + (i >> 5)] = word;
}

__global__ void __launch_bounds__(256) w3t_kernel(const float* __restrict__ w3)
{
    int i = blockIdx.x * 256 + threadIdx.x;   // 48000
    if (i < 48000) {
        int k = i / 120, o = i % 120;
        g_w3t[i] = w3[o * 400 + k];
    }
}

// ---------------- shared memory map (float offsets) ----------------
#define SM_XF     0        // 1024 input spikes
#define SM_M12A   1024     // 9408 layer1 m1,m2 interleaved (4704x2)
#define SM_SKB    10432    // 1176 pooled layer2 spikes
#define SM_M12C   11608    // 3200 conv2-out m1,m2 interleaved (1600x2)
#define SM_PARTB  14808    // 1600 conv2 half-ic partials (400x4)
#define SM_PARTC  16408    // 360  conv3 split partials (3x120)
#define SM_SKE    16768    // 120
#define SM_M12F   16888    // 168  fc1 m1,m2 (84x2)
#define SM_SKF    17056    // 84
#define SM_M12G   17140    // 20
#define SM_ACC    17160    // 10
#define SM_WCNT   17170    // 25 (ints)
#define SM_CNT    17196    // 1 (int)
#define SM_LIST   17198    // 400 (ints)
#define SM_W1     17598    // 150
#define SM_W2     17748    // 2400
#define SM_FW1    20148    // 10080
#define SM_FW2    30228    // 840
#define SM_TOTAL  31068
#define SMEM_BYTES (SM_TOTAL * 4)
#define SM_ZBEG   SM_M12A
#define SM_ZEND   SM_W1

__global__ void __launch_bounds__(1024, 1)
sim_kernel(const float* __restrict__ w1, const float* __restrict__ w2,
           const float* __restrict__ fw1, const float* __restrict__ fw2,
           float* __restrict__ out)
{
    extern __shared__ float sm[];
    int* const wcnt = (int*)(sm + SM_WCNT);
    int* const cnt  = (int*)(sm + SM_CNT);
    int* const list = (int*)(sm + SM_LIST);

    const int tid  = threadIdx.x;
    const int b    = blockIdx.x;
    const int lane = tid & 31;
    const int wrp  = tid >> 5;

    for (int i = tid; i < 150;   i += 1024) sm[SM_W1  + i] = w1[i];
    for (int i = tid; i < 2400;  i += 1024) sm[SM_W2  + i] = w2[i];
    for (int i = tid; i < 10080; i += 1024) sm[SM_FW1 + i] = fw1[i];
    for (int i = tid; i < 840;   i += 1024) sm[SM_FW2 + i] = fw2[i];
    for (int i = tid; i < (SM_ZEND - SM_ZBEG); i += 1024) sm[SM_ZBEG + i] = 0.0f;
    __syncthreads();

    // ---- static mappings ----
    // phase A: tid<588 : c(6) x by(14) x p(7 pooled-x pairs)
    const int a_c  = tid / 98;
    const int a_r  = tid % 98;
    const int a_by = a_r / 7;
    const int a_p  = a_r % 7;
    // phase B: tid<800 : oc(16) x blk(25) x half(2)
    const int b_oc  = tid / 50;
    const int b_rem = tid % 50;
    const int b_blk = b_rem >> 1;
    const int b_hf  = b_rem & 1;
    const int b_py  = b_blk / 5;
    const int b_px  = b_blk % 5;
    // phase C: tid<512 : split(4) x o(128, valid<120)
    const int c_sp = tid >> 7;
    const int c_o  = tid & 127;
    // phase D: tid<672 : g(84) x j(8)
    const int d_g = tid >> 3;
    const int d_j = tid & 7;

    // register-resident LIF state
    float pm1[2] = {0.f, 0.f}, pm2[2] = {0.f, 0.f};   // layer2 pooled (phase A)
    float qm1 = 0.f, qm2 = 0.f;                        // layer4 pooled (phase B owner)
    float em1 = 0.f, em2 = 0.f;                        // layer5 (tid<120)

    const unsigned* spk_base = g_spk + b * 32;

#pragma unroll 1
    for (int t = 0; t < T_STEPS; t++) {
        // ---- P0: expand input spikes ----
        {
            unsigned w = __ldg(spk_base + (unsigned)t * 1024u + wrp);
            sm[SM_XF + tid] = (float)((w >> lane) & 1u);
        }
        __syncthreads();

        // ---- A: conv1 + lif1 + pool + lif2 -> SKB ----
        if (tid < 588) {
            const float* wr = sm + SM_W1 + a_c * 25;
#pragma unroll
            for (int half = 0; half < 2; half++) {
                int px = 2 * a_p + half;
                int x0 = 2 * px;
                float in[6][6];
#pragma unroll
                for (int ry = 0; ry < 6; ry++) {
                    const float* row = sm + SM_XF + (2 * a_by + ry) * 32 + x0;
#pragma unroll
                    for (int rx = 0; rx < 6; rx += 2) {
                        float2 v = *(const float2*)(row + rx);
                        in[ry][rx] = v.x; in[ry][rx + 1] = v.y;
                    }
                }
                float acc[4] = {0.f, 0.f, 0.f, 0.f};
#pragma unroll
                for (int ky = 0; ky < 5; ky++)
#pragma unroll
                    for (int kx = 0; kx < 5; kx++) {
                        float wv = wr[ky * 5 + kx];
                        acc[0] = fmaf(wv, in[ky][kx],         acc[0]);
                        acc[1] = fmaf(wv, in[ky][kx + 1],     acc[1]);
                        acc[2] = fmaf(wv, in[ky + 1][kx],     acc[2]);
                        acc[3] = fmaf(wv, in[ky + 1][kx + 1], acc[3]);
                    }
                float psum = 0.f;
#pragma unroll
                for (int q = 0; q < 4; q++) {
                    int o = a_c * 784 + (2 * a_by + (q >> 1)) * 28 + x0 + (q & 1);
                    float2 m = *(float2*)(sm + SM_M12A + 2 * o);
                    float oms = (m.y > 0.3f) ? 0.f : 1.f;
                    float nm1 = m.x * 0.25f * oms + acc[q];
                    float nm2 = m.y * 0.25f * oms + 0.5f * nm1;
                    *(float2*)(sm + SM_M12A + 2 * o) = make_float2(nm1, nm2);
                    psum += (nm2 > 0.3f) ? 1.f : 0.f;
                }
                float d   = 0.25f * psum;
                float oms = (pm2[half] > 0.3f) ? 0.f : 1.f;
                float nm1 = pm1[half] * 0.25f * oms + d;
                float nm2 = pm2[half] * 0.25f * oms + 0.5f * nm1;
                pm1[half] = nm1; pm2[half] = nm2;
                sm[SM_SKB + a_c * 196 + a_by * 14 + px] = (nm2 > 0.3f) ? 1.f : 0.f;
            }
        }
        __syncthreads();

        // ---- B1: conv2 half-ic partials ----
        float bacc[4] = {0.f, 0.f, 0.f, 0.f};
        if (tid < 800) {
#pragma unroll
            for (int ic3 = 0; ic3 < 3; ic3++) {
                int ic = b_hf * 3 + ic3;
                const float* ib = sm + SM_SKB + ic * 196 + 2 * b_py * 14 + 2 * b_px;
                const float* wr = sm + SM_W2 + b_oc * 150 + ic * 25;
                float in[6][6];
#pragma unroll
                for (int ry = 0; ry < 6; ry++) {
                    const float* row = ib + ry * 14;
#pragma unroll
                    for (int rx = 0; rx < 6; rx += 2) {
                        float2 v = *(const float2*)(row + rx);
                        in[ry][rx] = v.x; in[ry][rx + 1] = v.y;
                    }
                }
#pragma unroll
                for (int ky = 0; ky < 5; ky++)
#pragma unroll
                    for (int kx = 0; kx < 5; kx++) {
                        float wv = wr[ky * 5 + kx];
                        bacc[0] = fmaf(wv, in[ky][kx],         bacc[0]);
                        bacc[1] = fmaf(wv, in[ky][kx + 1],     bacc[1]);
                        bacc[2] = fmaf(wv, in[ky + 1][kx],     bacc[2]);
                        bacc[3] = fmaf(wv, in[ky + 1][kx + 1], bacc[3]);
                    }
            }
            if (b_hf) {
                float* pp = sm + SM_PARTB + (b_oc * 25 + b_blk) * 4;
#pragma unroll
                for (int q = 0; q < 4; q++) pp[q] = bacc[q];
            }
        }
        __syncthreads();

        // ---- B2: combine + lif3 + pool + lif4; warp spike counts ----
        int myk = -1, mypos = 0;
        if (tid < 800) {
            if (!b_hf) {
                const float* pp = sm + SM_PARTB + (b_oc * 25 + b_blk) * 4;
                float psum = 0.f;
#pragma unroll
                for (int q = 0; q < 4; q++) {
                    float drive = bacc[q] + pp[q];
                    int o = b_oc * 100 + (2 * b_py + (q >> 1)) * 10 + 2 * b_px + (q & 1);
                    float2 m = *(float2*)(sm + SM_M12C + 2 * o);
                    float oms = (m.y > 0.3f) ? 0.f : 1.f;
                    float nm1 = m.x * 0.25f * oms + drive;
                    float nm2 = m.y * 0.25f * oms + 0.5f * nm1;
                    *(float2*)(sm + SM_M12C + 2 * o) = make_float2(nm1, nm2);
                    psum += (nm2 > 0.3f) ? 1.f : 0.f;
                }
                float d   = 0.25f * psum;
                float oms = (qm2 > 0.3f) ? 0.f : 1.f;
                float nm1 = qm1 * 0.25f * oms + d;
                float nm2 = qm2 * 0.25f * oms + 0.5f * nm1;
                qm1 = nm1; qm2 = nm2;
                if (nm2 > 0.3f) myk = b_oc * 25 + b_blk;
            }
            unsigned m = __ballot_sync(0xffffffffu, myk >= 0);
            mypos = __popc(m & ((1u << lane) - 1u));
            if (lane == 0) wcnt[wrp] = __popc(m);
        }
        __syncthreads();

        // ---- L: deterministic list compaction ----
        if (tid < 800 && myk >= 0) {
            int base = 0;
            for (int w2 = 0; w2 < wrp; w2++) base += wcnt[w2];
            list[base + mypos] = myk;
        }
        if (tid == 0) {
            int a = 0;
#pragma unroll
            for (int w2 = 0; w2 < 25; w2++) a += wcnt[w2];
            *cnt = a;
        }
        __syncthreads();

        // ---- C1: sparse conv3 gather (4-way k split) ----
        float cacc = 0.f;
        if (tid < 512 && c_o < 120) {
            int A = *cnt;
            for (int j = c_sp; j < A; j += 4) {
                int k = list[j];
                cacc += __ldg(g_w3t + k * 120 + c_o);
            }
            if (c_sp) sm[SM_PARTC + (c_sp - 1) * 120 + c_o] = cacc;
        }
        __syncthreads();

        // ---- C2: combine + lif5 -> SKE ----
        if (tid < 120) {
            float d = cacc + sm[SM_PARTC + tid] + sm[SM_PARTC + 120 + tid]
                           + sm[SM_PARTC + 240 + tid];
            float oms = (em2 > 0.3f) ? 0.f : 1.f;
            float nm1 = em1 * 0.25f * oms + d;
            float nm2 = em2 * 0.25f * oms + 0.5f * nm1;
            em1 = nm1; em2 = nm2;
            sm[SM_SKE + tid] = (nm2 > 0.3f) ? 1.f : 0.f;
        }
        __syncthreads();

        // ---- D: fc1 + lif6 -> SKF ----
        if (tid < 672) {
            const float* wp = sm + SM_FW1 + d_g * 120;
            float s = 0.f;
#pragma unroll
            for (int k = d_j; k < 120; k += 8) s = fmaf(wp[k], sm[SM_SKE + k], s);
            s += __shfl_xor_sync(0xffffffffu, s, 4);
            s += __shfl_xor_sync(0xffffffffu, s, 2);
            s += __shfl_xor_sync(0xffffffffu, s, 1);
            if (d_j == 0) {
                float2 m = *(float2*)(sm + SM_M12F + 2 * d_g);
                float oms = (m.y > 0.3f) ? 0.f : 1.f;
                float nm1 = m.x * 0.25f * oms + s;
                float nm2 = m.y * 0.25f * oms + 0.5f * nm1;
                *(float2*)(sm + SM_M12F + 2 * d_g) = make_float2(nm1, nm2);
                sm[SM_SKF + d_g] = (nm2 > 0.3f) ? 1.f : 0.f;
            }
        }
        __syncthreads();

        // ---- E: fc2 + lif7 + acc ----
        if (wrp < 10) {
            const float* wp = sm + SM_FW2 + wrp * 84;
            float s = 0.f;
            for (int k = lane; k < 84; k += 32) s = fmaf(wp[k], sm[SM_SKF + k], s);
#pragma unroll
            for (int d2 = 16; d2 > 0; d2 >>= 1) s += __shfl_xor_sync(0xffffffffu, s, d2);
            if (lane == 0) {
                float2 m = *(float2*)(sm + SM_M12G + 2 * wrp);
                float oms = (m.y > 0.3f) ? 0.f : 1.f;
                float nm1 = m.x * 0.25f * oms + s;
                float nm2 = m.y * 0.25f * oms + 0.5f * nm1;
                *(float2*)(sm + SM_M12G + 2 * wrp) = make_float2(nm1, nm2);
                sm[SM_ACC + wrp] += (nm2 > 0.3f) ? 1.f : 0.f;
            }
        }
        __syncthreads();
    }

    if (tid < 10)
        out[b * 10 + tid] = sm[SM_ACC + tid] * (1.0f / 512.0f);
}

extern "C" void kernel_launch(void* const* d_in, const int* in_sizes, int n_in,
                              void* d_out, int out_size)
{
    const float* image = (const float*)d_in[0];
    const float* w1    = (const float*)d_in[1];
    const float* w2    = (const float*)d_in[2];
    const float* w3    = (const float*)d_in[3];
    const float* fw1   = (const float*)d_in[4];
    const float* fw2   = (const float*)d_in[5];
    float* out = (float*)d_out;

    keys_kernel<<<1, 512>>>();
    spikes_kernel<<<(T_STEPS * 32768) / 256, 256>>>(image);
    w3t_kernel<<<(48000 + 255) / 256, 256>>>(w3);
    cudaFuncSetAttribute(sim_kernel, cudaFuncAttributeMaxDynamicSharedMemorySize, SMEM_BYTES);
    sim_kernel<<<32, 1024, SMEM_BYTES>>>(w1, w2, fw1, fw2, out);
}